// round 5
// baseline (speedup 1.0000x reference)
#include <cuda_runtime.h>
#include <cstdint>

// BP-MLL loss, B=8192 rows x L=10000 cols, fp32 input, int32 target in {0,1}.
//   row value = (sum_{t==1} exp(-x)) * (sum_{t==0} exp(x)) / (n_pos * n_neg)
//   output    = sum over rows (scalar).
//
// Single fused kernel: one CTA per row computes its row value into __device__
// scratch; the LAST CTA to finish (threadfence-reduction pattern) sums all
// row values in a FIXED order (deterministic regardless of completion order)
// and writes d_out[0]. Arrival counter resets every run -> graph-replay safe.
// Graph-capturable, allocation-free. No wait loops anywhere (no hang risk).

#define ROWS_MAX 8192
#define L_COLS   10000
#define VEC      (L_COLS / 4)   // 2500 float4 / int4 per row
#define BLK      256

__device__ float        g_row_vals[ROWS_MAX];
__device__ unsigned int g_arrive = 0;

__device__ __forceinline__ float warp_sum(float v) {
    #pragma unroll
    for (int o = 16; o > 0; o >>= 1)
        v += __shfl_down_sync(0xffffffffu, v, o);
    return v;
}
__device__ __forceinline__ int warp_sum_i(int v) {
    #pragma unroll
    for (int o = 16; o > 0; o >>= 1)
        v += __shfl_down_sync(0xffffffffu, v, o);
    return v;
}

__global__ void __launch_bounds__(BLK)
bpmll_fused_kernel(const float* __restrict__ x,
                   const int*   __restrict__ t,
                   float*       __restrict__ out,
                   int rows)
{
    const int row = blockIdx.x;
    const float4* __restrict__ xr =
        reinterpret_cast<const float4*>(x + (size_t)row * L_COLS);
    const int4* __restrict__ tr =
        reinterpret_cast<const int4*>(t + (size_t)row * L_COLS);

    float tot = 0.0f;  // sum over all elems of exp(sign-folded x)  (= sp + sn)
    float sp  = 0.0f;  // sum over positives of exp(-x)
    int   np  = 0;     // positive count

    #pragma unroll 2
    for (int i = threadIdx.x; i < VEC; i += BLK) {
        const float4 xv = __ldcs(xr + i);   // read-once: evict-first
        const int4   tv = __ldcs(tr + i);

        // y = (t==1) ? -x : x via sign-bit XOR, one exp per element.
        {
            const unsigned s = (unsigned)tv.x * 0x80000000u;
            const float e = __expf(__int_as_float(__float_as_int(xv.x) ^ s));
            tot += e;  sp += tv.x ? e : 0.0f;
        }
        {
            const unsigned s = (unsigned)tv.y * 0x80000000u;
            const float e = __expf(__int_as_float(__float_as_int(xv.y) ^ s));
            tot += e;  sp += tv.y ? e : 0.0f;
        }
        {
            const unsigned s = (unsigned)tv.z * 0x80000000u;
            const float e = __expf(__int_as_float(__float_as_int(xv.z) ^ s));
            tot += e;  sp += tv.z ? e : 0.0f;
        }
        {
            const unsigned s = (unsigned)tv.w * 0x80000000u;
            const float e = __expf(__int_as_float(__float_as_int(xv.w) ^ s));
            tot += e;  sp += tv.w ? e : 0.0f;
        }
        np += (tv.x + tv.y) + (tv.z + tv.w);
    }

    // Block reduction: warp shuffle, then warp 0 over per-warp partials.
    __shared__ float s_tot[BLK / 32];
    __shared__ float s_sp[BLK / 32];
    __shared__ int   s_np[BLK / 32];
    __shared__ bool  s_is_last;

    const int lane = threadIdx.x & 31;
    const int wid  = threadIdx.x >> 5;

    tot = warp_sum(tot);
    sp  = warp_sum(sp);
    np  = warp_sum_i(np);
    if (lane == 0) { s_tot[wid] = tot; s_sp[wid] = sp; s_np[wid] = np; }
    __syncthreads();

    if (wid == 0) {
        tot = (lane < BLK / 32) ? s_tot[lane] : 0.0f;
        sp  = (lane < BLK / 32) ? s_sp[lane]  : 0.0f;
        np  = (lane < BLK / 32) ? s_np[lane]  : 0;
        tot = warp_sum(tot);
        sp  = warp_sum(sp);
        np  = warp_sum_i(np);
        if (lane == 0) {
            const float sn = tot - sp;
            const float k  = (float)np * (float)(L_COLS - np);
            g_row_vals[row] = sp * sn / k;
        }
    }

    // ---- threadfence reduction: last CTA sums all rows in fixed order ----
    __threadfence();
    if (threadIdx.x == 0) {
        const unsigned ticket = atomicAdd(&g_arrive, 1u);
        s_is_last = (ticket == (unsigned)(rows - 1));
    }
    __syncthreads();

    if (s_is_last) {
        // Every other CTA has already taken its ticket; reset is race-free
        // and off the critical path of the sum below.
        if (threadIdx.x == BLK - 1) g_arrive = 0;

        // Fixed-order summation: thread tid sums indices {tid, tid+BLK, ...},
        // then a fixed-shape shuffle/shared tree. Bitwise identical result
        // regardless of which block executes it -> deterministic.
        float s = 0.0f;
        for (int i = threadIdx.x; i < rows; i += BLK)
            s += g_row_vals[i];

        __shared__ float sm[BLK / 32];
        s = warp_sum(s);
        if (lane == 0) sm[wid] = s;
        __syncthreads();
        if (wid == 0) {
            s = (lane < BLK / 32) ? sm[lane] : 0.0f;
            s = warp_sum(s);
            if (lane == 0) out[0] = s;
        }
    }
}

extern "C" void kernel_launch(void* const* d_in, const int* in_sizes, int n_in,
                              void* d_out, int out_size)
{
    const float* x = (const float*)d_in[0];
    const int*   t = (const int*)d_in[1];
    float* out = (float*)d_out;

    const int rows = in_sizes[0] / L_COLS;   // 8192

    bpmll_fused_kernel<<<rows, BLK>>>(x, t, out, rows);
}

// round 6
// speedup vs baseline: 1.0172x; 1.0172x over previous
#include <cuda_runtime.h>
#include <cstdint>

// BP-MLL loss, B=8192 rows x L=10000 cols, fp32 input, int32 target in {0,1}.
//   row value = (sum_{t==1} exp(-x)) * (sum_{t==0} exp(x)) / (n_pos * n_neg)
//   output    = sum over rows (scalar).
//
// One CTA per row. Hierarchical deterministic reduction:
//   - each CTA writes its row value to g_row_vals[row]
//   - the CTA that completes the 128th row of a 128-row group sums that group
//     (fixed order) into g_grp_vals[group]  -- overlapped with remaining rows
//   - the CTA that completes the 64th group sums the 64 group values (fixed
//     order) into d_out[0] and resets counters for the next graph replay.
// All sums use fixed shapes/orders -> bitwise deterministic regardless of
// completion order. Graph-capturable, allocation-free, no spin loops.

#define ROWS_MAX 8192
#define L_COLS   10000
#define VEC      (L_COLS / 4)   // 2500 float4 / int4 per row
#define BLK      256
#define GRP_SZ   128
#define N_GRP    (ROWS_MAX / GRP_SZ)   // 64

__device__ float        g_row_vals[ROWS_MAX];
__device__ float        g_grp_vals[N_GRP];
__device__ unsigned int g_grp_cnt[N_GRP];   // zero-initialized; reset each run
__device__ unsigned int g_grp_done = 0;     // reset each run

__device__ __forceinline__ float warp_sum(float v) {
    #pragma unroll
    for (int o = 16; o > 0; o >>= 1)
        v += __shfl_down_sync(0xffffffffu, v, o);
    return v;
}
__device__ __forceinline__ int warp_sum_i(int v) {
    #pragma unroll
    for (int o = 16; o > 0; o >>= 1)
        v += __shfl_down_sync(0xffffffffu, v, o);
    return v;
}

__global__ void __launch_bounds__(BLK)
bpmll_fused_kernel(const float* __restrict__ x,
                   const int*   __restrict__ t,
                   float*       __restrict__ out,
                   int rows)
{
    const int row = blockIdx.x;
    const float4* __restrict__ xr =
        reinterpret_cast<const float4*>(x + (size_t)row * L_COLS);
    const int4* __restrict__ tr =
        reinterpret_cast<const int4*>(t + (size_t)row * L_COLS);

    float tot = 0.0f;  // sum over all elems of exp(sign-folded x)  (= sp + sn)
    float sp  = 0.0f;  // sum over positives of exp(-x)
    int   np  = 0;     // positive count

    #pragma unroll 2
    for (int i = threadIdx.x; i < VEC; i += BLK) {
        const float4 xv = __ldcs(xr + i);   // read-once: evict-first
        const int4   tv = __ldcs(tr + i);

        // y = (t==1) ? -x : x via sign-bit XOR, one exp per element.
        {
            const unsigned s = (unsigned)tv.x * 0x80000000u;
            const float e = __expf(__int_as_float(__float_as_int(xv.x) ^ s));
            tot += e;  sp += tv.x ? e : 0.0f;
        }
        {
            const unsigned s = (unsigned)tv.y * 0x80000000u;
            const float e = __expf(__int_as_float(__float_as_int(xv.y) ^ s));
            tot += e;  sp += tv.y ? e : 0.0f;
        }
        {
            const unsigned s = (unsigned)tv.z * 0x80000000u;
            const float e = __expf(__int_as_float(__float_as_int(xv.z) ^ s));
            tot += e;  sp += tv.z ? e : 0.0f;
        }
        {
            const unsigned s = (unsigned)tv.w * 0x80000000u;
            const float e = __expf(__int_as_float(__float_as_int(xv.w) ^ s));
            tot += e;  sp += tv.w ? e : 0.0f;
        }
        np += (tv.x + tv.y) + (tv.z + tv.w);
    }

    // ---- block reduction for this row ----
    __shared__ float s_tot[BLK / 32];
    __shared__ float s_sp[BLK / 32];
    __shared__ int   s_np[BLK / 32];
    __shared__ int   s_close_grp;
    __shared__ int   s_final;

    const int lane = threadIdx.x & 31;
    const int wid  = threadIdx.x >> 5;

    tot = warp_sum(tot);
    sp  = warp_sum(sp);
    np  = warp_sum_i(np);
    if (lane == 0) { s_tot[wid] = tot; s_sp[wid] = sp; s_np[wid] = np; }
    __syncthreads();

    if (wid == 0) {
        tot = (lane < BLK / 32) ? s_tot[lane] : 0.0f;
        sp  = (lane < BLK / 32) ? s_sp[lane]  : 0.0f;
        np  = (lane < BLK / 32) ? s_np[lane]  : 0;
        tot = warp_sum(tot);
        sp  = warp_sum(sp);
        np  = warp_sum_i(np);
        if (lane == 0) {
            const float sn = tot - sp;
            const float k  = (float)np * (float)(L_COLS - np);
            g_row_vals[row] = sp * sn / k;
        }
    }

    // ---- level 1: group arrival (128 rows per group) ----
    __threadfence();
    if (threadIdx.x == 0) {
        const unsigned c = atomicAdd(&g_grp_cnt[row >> 7], 1u);
        s_close_grp = (c == GRP_SZ - 1u);
    }
    __syncthreads();

    if (!s_close_grp) return;

    // This CTA closes group g: sum its 128 row values in a FIXED order.
    const int g    = row >> 7;
    const int base = g << 7;
    float gs = 0.0f;
    if (wid == 0) {
        gs = (g_row_vals[base + lane]      + g_row_vals[base + 64 + lane]) +
             (g_row_vals[base + 32 + lane] + g_row_vals[base + 96 + lane]);
        gs = warp_sum(gs);   // total in lane 0
    }
    if (threadIdx.x == 0) {
        g_grp_vals[g] = gs;
        __threadfence();
        const unsigned d = atomicAdd(&g_grp_done, 1u);
        s_final = (d == N_GRP - 1u);
    }
    __syncthreads();

    if (!s_final) return;

    // ---- level 2: final sum over 64 group values (fixed order) ----
    if (wid == 0) {
        float f = g_grp_vals[lane] + g_grp_vals[32 + lane];
        f = warp_sum(f);
        if (lane == 0) out[0] = f;
    }
    // Reset counters for the next graph replay. Safe: every atomicAdd on
    // g_grp_cnt happens-before its group's g_grp_done increment, and we only
    // get here after the 64th increment -- no counter is touched again this run.
    if (threadIdx.x >= 32 && threadIdx.x < 32 + N_GRP)
        g_grp_cnt[threadIdx.x - 32] = 0;
    if (threadIdx.x == 96)
        g_grp_done = 0;
}

extern "C" void kernel_launch(void* const* d_in, const int* in_sizes, int n_in,
                              void* d_out, int out_size)
{
    const float* x = (const float*)d_in[0];
    const int*   t = (const int*)d_in[1];
    float* out = (float*)d_out;

    const int rows = in_sizes[0] / L_COLS;   // 8192

    bpmll_fused_kernel<<<rows, BLK>>>(x, t, out, rows);
}